// round 3
// baseline (speedup 1.0000x reference)
#include <cuda_runtime.h>
#include <math.h>

#define NB 128
#define NJ 32
#define NI 1152
#define NN 16
#define TI 32
#define NTILES 36
#define DSTR 33

// ---------- global scratch ----------
__device__ float    g_V0[NB * NJ * NN];
__device__ float    g_V1[NB * NJ * NN];
__device__ float    g_VW[NB * NJ * NN];                // v0 + v1
__device__ float    g_S_part[NTILES * NB * NJ * NN];
__device__ float    g_sc_part[NTILES * NB * NJ];
__device__ float    g_ent_part[2 * NTILES * NB];
__device__ unsigned g_mask1[NB];
__device__ unsigned g_mask2[NB];
__device__ int      g_cnt[4 * NB];

__device__ __forceinline__ float wsum32(float v) {
#pragma unroll
    for (int o = 16; o; o >>= 1) v += __shfl_xor_sync(0xFFFFFFFFu, v, o);
    return v;
}
__device__ __forceinline__ float wmax32(float v) {
#pragma unroll
    for (int o = 16; o; o >>= 1) v = fmaxf(v, __shfl_xor_sync(0xFFFFFFFFu, v, o));
    return v;
}

// =====================================================================
// Pass 1: s0 = (1/32)*sum_i u ; v0 = squash(s0+bias). Also zeroes counters.
// =====================================================================
__global__ void __launch_bounds__(256) pass1_kernel(const float* __restrict__ u,
                                                    const float* __restrict__ bias) {
    __shared__ float sred[64 * 17];
    int j = blockIdx.x, b = blockIdx.y;
    int t = threadIdx.x;
    if (j == 0 && t < 4) g_cnt[t * NB + b] = 0;   // reset epilogue counters
    int q = t & 3, ir = t >> 2;
    const float* base = u + (size_t)(b * NJ + j) * (NI * NN);
    float4 acc = make_float4(0.f, 0.f, 0.f, 0.f);
#pragma unroll
    for (int k = 0; k < 18; ++k) {
        int i = ir + k * 64;
        float4 v = *reinterpret_cast<const float4*>(base + (size_t)i * NN + q * 4);
        acc.x += v.x; acc.y += v.y; acc.z += v.z; acc.w += v.w;
    }
    float* sp = sred + ir * 17 + q * 4;
    sp[0] = acc.x; sp[1] = acc.y; sp[2] = acc.z; sp[3] = acc.w;
    __syncthreads();
    if (t < 16) {
        int n = t;
        float s = 0.f;
        for (int r = 0; r < 64; ++r) s += sred[r * 17 + n];
        s *= (1.f / 32.f);
        float ss = s;
#pragma unroll
        for (int o = 8; o; o >>= 1) ss += __shfl_xor_sync(0xFFFFu, ss, o);
        float tb = (ss == 0.f) ? 0.f : (s + bias[j * NN + n]);
        float sq = tb * tb;
#pragma unroll
        for (int o = 8; o; o >>= 1) sq += __shfl_xor_sync(0xFFFFu, sq, o);
        float v = (sq / (1.f + sq)) * tb / sqrtf(sq + 1e-8f);
        g_V0[(b * NJ + j) * NN + n] = v;
    }
}

// =====================================================================
// SCORE pass: one u sweep; register dots d = u·v, masked softmax,
// node-score partials; fused last-block top-K -> mask.
// =====================================================================
__global__ void __launch_bounds__(256) score_kernel(const float* __restrict__ u,
                                                    const float* __restrict__ vglob,
                                                    int mask_sel, int cnt_slot,
                                                    int K, int which) {
    __shared__ float sd[32 * DSTR];
    __shared__ int s_last;
    int t = threadIdx.x, lane = t & 31, w = t >> 5;
    int tb = blockIdx.x, b = blockIdx.y, i0 = tb * TI;
    int q = lane & 3, ig = lane >> 2;
    const float* ub = u + (size_t)b * (NJ * NI * NN);

#pragma unroll
    for (int p = 0; p < 4; ++p) {
        int j = w * 4 + p;
        float4 vj = *reinterpret_cast<const float4*>(vglob + (b * NJ + j) * NN + q * 4);
#pragma unroll
        for (int m = 0; m < 4; ++m) {
            int il = m * 8 + ig;
            float4 r = *reinterpret_cast<const float4*>(
                ub + (size_t)j * (NI * NN) + (size_t)(i0 + il) * NN + q * 4);
            float d = r.x * vj.x + r.y * vj.y + r.z * vj.z + r.w * vj.w;
            d += __shfl_xor_sync(0xFFFFFFFFu, d, 1);
            d += __shfl_xor_sync(0xFFFFFFFFu, d, 2);
            if (q == 0) sd[il * DSTR + j] = d;
        }
    }
    unsigned msk = mask_sel ? g_mask1[b] : 0xFFFFFFFFu;
    __syncthreads();

#pragma unroll
    for (int s = 0; s < 4; ++s) {
        int il = w * 4 + s;
        float d = sd[il * DSTR + lane];
        bool sel = (msk >> lane) & 1u;
        float mx = wmax32(sel ? d : -INFINITY);
        float e = sel ? expf(d - mx) : 0.f;
        float S = wsum32(e);
        sd[il * DSTR + lane] = e / S;
    }
    __syncthreads();

#pragma unroll
    for (int p = 0; p < 4; ++p) {
        int j = w * 4 + p;
        float c = wsum32(sd[lane * DSTR + j]);
        if (lane == 0) g_sc_part[tb * (NB * NJ) + b * NJ + j] = c;
    }
    __threadfence();
    __syncthreads();
    if (t == 0) s_last = (atomicAdd(&g_cnt[cnt_slot * NB + b], 1) == NTILES - 1);
    __syncthreads();
    if (!s_last || w) return;

    // last block for this b: top-K over summed node scores (warp 0)
    float sc = 0.f;
#pragma unroll 6
    for (int tt = 0; tt < NTILES; ++tt) sc += __ldcg(&g_sc_part[tt * (NB * NJ) + b * NJ + lane]);
    int rank = 0;
#pragma unroll
    for (int k = 0; k < 32; ++k) {
        float o = __shfl_sync(0xFFFFFFFFu, sc, k);
        rank += (o > sc) || (o == sc && k < lane);
    }
    unsigned m = __ballot_sync(0xFFFFFFFFu, rank < K);
    if (lane == 0) { if (which == 1) g_mask1[b] = m; else g_mask2[b] = m; }
}

// =====================================================================
// SUM pass: ONE u sweep. Per 8-row i-group: register dots -> smem,
// balanced softmax (+entropy), then s-accum from the register-held u.
// Fused last-block squash (-> v1 & w=v0+v1, or final out + entropies).
// =====================================================================
template <bool IS_FINAL>
__global__ void __launch_bounds__(256, 3) sum_kernel(const float* __restrict__ u,
                                                     const float* __restrict__ vglob,
                                                     const float* __restrict__ bias,
                                                     float* __restrict__ out,
                                                     int mask_sel, int ent_slot,
                                                     int cnt_slot) {
    __shared__ float sd[32 * DSTR];
    __shared__ float red[8];
    __shared__ int s_last;
    int t = threadIdx.x, lane = t & 31, w = t >> 5;
    int tb = blockIdx.x, b = blockIdx.y, i0 = tb * TI;
    int q = lane & 3, ig = lane >> 2;
    const float* ub = u + (size_t)b * (NJ * NI * NN);

    float4 vj[4];
#pragma unroll
    for (int p = 0; p < 4; ++p)
        vj[p] = *reinterpret_cast<const float4*>(vglob + (b * NJ + w * 4 + p) * NN + q * 4);
    unsigned msk = (mask_sel == 1) ? g_mask1[b] : g_mask2[b];

    float4 rcur[4], rnxt[4];
#pragma unroll
    for (int p = 0; p < 4; ++p)
        rcur[p] = *reinterpret_cast<const float4*>(
            ub + (size_t)(w * 4 + p) * (NI * NN) + (size_t)(i0 + ig) * NN + q * 4);

    float4 acc[4];
#pragma unroll
    for (int p = 0; p < 4; ++p) acc[p] = make_float4(0.f, 0.f, 0.f, 0.f);
    float ent_acc = 0.f;

#pragma unroll
    for (int m = 0; m < 4; ++m) {
        int il = m * 8 + ig;
        // dots from registers
#pragma unroll
        for (int p = 0; p < 4; ++p) {
            float4 r = rcur[p];
            float d = r.x * vj[p].x + r.y * vj[p].y + r.z * vj[p].z + r.w * vj[p].w;
            d += __shfl_xor_sync(0xFFFFFFFFu, d, 1);
            d += __shfl_xor_sync(0xFFFFFFFFu, d, 2);
            if (q == 0) sd[il * DSTR + w * 4 + p] = d;
        }
        // prefetch next group (overlaps softmax)
        if (m < 3) {
            int iln = (m + 1) * 8 + ig;
#pragma unroll
            for (int p = 0; p < 4; ++p)
                rnxt[p] = *reinterpret_cast<const float4*>(
                    ub + (size_t)(w * 4 + p) * (NI * NN) + (size_t)(i0 + iln) * NN + q * 4);
        }
        __syncthreads();
        // softmax: warp w handles row m*8+w (1 row/warp, balanced)
        {
            int il2 = m * 8 + w;
            float d = sd[il2 * DSTR + lane];
            bool sel = (msk >> lane) & 1u;
            float mx = wmax32(sel ? d : -INFINITY);
            float e = sel ? expf(d - mx) : 0.f;
            float S = wsum32(e);
            float c = e / S;
            sd[il2 * DSTR + lane] = c;
            float cds = wsum32(sel ? c * d : 0.f);
            ent_acc += (mx + logf(S) - cds);
        }
        __syncthreads();
        // s-accum from held registers
#pragma unroll
        for (int p = 0; p < 4; ++p) {
            float c = sd[il * DSTR + w * 4 + p];
            acc[p].x += c * rcur[p].x;
            acc[p].y += c * rcur[p].y;
            acc[p].z += c * rcur[p].z;
            acc[p].w += c * rcur[p].w;
        }
#pragma unroll
        for (int p = 0; p < 4; ++p) rcur[p] = rnxt[p];
    }

    // reduce acc over the 8 ig groups, write s partials
#pragma unroll
    for (int p = 0; p < 4; ++p) {
#pragma unroll
        for (int o = 4; o < 32; o <<= 1) {
            acc[p].x += __shfl_xor_sync(0xFFFFFFFFu, acc[p].x, o);
            acc[p].y += __shfl_xor_sync(0xFFFFFFFFu, acc[p].y, o);
            acc[p].z += __shfl_xor_sync(0xFFFFFFFFu, acc[p].z, o);
            acc[p].w += __shfl_xor_sync(0xFFFFFFFFu, acc[p].w, o);
        }
        if (ig == 0) {
            size_t so = (size_t)tb * (NB * NJ * NN) + (size_t)(b * NJ + w * 4 + p) * NN + q * 4;
            *reinterpret_cast<float4*>(g_S_part + so) = acc[p];
        }
    }
    if (lane == 0) red[w] = ent_acc;
    __syncthreads();
    if (t == 0) {
        float e = 0.f;
#pragma unroll
        for (int x = 0; x < 8; ++x) e += red[x];
        g_ent_part[ent_slot * (NTILES * NB) + tb * NB + b] = e;
    }
    __threadfence();
    __syncthreads();
    if (t == 0) s_last = (atomicAdd(&g_cnt[cnt_slot * NB + b], 1) == NTILES - 1);
    __syncthreads();
    if (!s_last) return;

    // squash epilogue (deterministic fixed-order tile sum)
#pragma unroll
    for (int e2 = 0; e2 < 2; ++e2) {
        int jn = t + e2 * 256;
        int gid = b * (NJ * NN) + jn;
        float s = 0.f;
#pragma unroll 6
        for (int tt = 0; tt < NTILES; ++tt)
            s += __ldcg(&g_S_part[(size_t)tt * (NB * NJ * NN) + gid]);
        float ss = s;
#pragma unroll
        for (int o = 8; o; o >>= 1) ss += __shfl_xor_sync(0xFFFFFFFFu, ss, o);
        int n = jn & 15, j = (jn >> 4) & 31;
        float tb2 = (ss == 0.f) ? 0.f : (s + bias[j * NN + n]);
        float sq = tb2 * tb2;
#pragma unroll
        for (int o = 8; o; o >>= 1) sq += __shfl_xor_sync(0xFFFFFFFFu, sq, o);
        float v = (sq / (1.f + sq)) * tb2 / sqrtf(sq + 1e-8f);
        if (IS_FINAL) out[gid] = v;
        else { g_V1[gid] = v; g_VW[gid] = g_V0[gid] + v; }
    }
    if (IS_FINAL && t == 0) {
        float e1 = 0.f, e2v = 0.f;
        for (int tt = 0; tt < NTILES; ++tt) {
            e1  += __ldcg(&g_ent_part[0 * (NTILES * NB) + tt * NB + b]);
            e2v += __ldcg(&g_ent_part[1 * (NTILES * NB) + tt * NB + b]);
        }
        float* eo = out + NB * NJ * NN;
        eo[b * 3 + 0] = logf(32.0f);
        eo[b * 3 + 1] = e1 * (1.f / (float)NI);
        eo[b * 3 + 2] = e2v * (1.f / (float)NI);
    }
}

// =====================================================================
extern "C" void kernel_launch(void* const* d_in, const int* in_sizes, int n_in,
                              void* d_out, int out_size) {
    const float* u    = (const float*)d_in[0];
    const float* bias = (const float*)d_in[1];
    float* out        = (float*)d_out;

    float *v0p, *vwp;
    cudaGetSymbolAddress((void**)&v0p, g_V0);
    cudaGetSymbolAddress((void**)&vwp, g_VW);

    dim3 sgrid(NTILES, NB);

    // sweep 1: s0 -> v0 (+counter reset)
    pass1_kernel<<<dim3(NJ, NB), 256>>>(u, bias);
    // sweep 2: scores of softmax(u·v0) -> top-20 -> mask1
    score_kernel<<<sgrid, 256>>>(u, v0p, 0, 0, 20, 1);
    // sweep 3: c1 = softmax(u·v0, mask1), entropy1, s1 -> v1, w = v0+v1
    sum_kernel<false><<<sgrid, 256>>>(u, v0p, bias, out, 1, 0, 1);
    // sweep 4: scores of softmax(u·w, mask1) -> top-12 -> mask2
    score_kernel<<<sgrid, 256>>>(u, vwp, 1, 2, 12, 2);
    // sweep 5: c2 = softmax(u·w, mask2), entropy2, s2 -> v2 (out) + entropies
    sum_kernel<true><<<sgrid, 256>>>(u, vwp, bias, out, 2, 1, 3);
}

// round 4
// speedup vs baseline: 1.2990x; 1.2990x over previous
#include <cuda_runtime.h>
#include <math.h>

#define NB 128
#define NJ 32
#define NI 1152
#define NN 16
#define TI 32
#define NTILES 36
#define DSTR 33

// ---------- global scratch ----------
__device__ float    g_V0[NB * NJ * NN];
__device__ float    g_V1[NB * NJ * NN];
__device__ float    g_VW[NB * NJ * NN];                // v0 + v1
__device__ float    g_S_part[NTILES * NB * NJ * NN];
__device__ float    g_sc_part[NTILES * NB * NJ];
__device__ float    g_ent_part[2 * NTILES * NB];
__device__ unsigned g_mask1[NB];
__device__ unsigned g_mask2[NB];

__device__ __forceinline__ float wsum32(float v) {
#pragma unroll
    for (int o = 16; o; o >>= 1) v += __shfl_xor_sync(0xFFFFFFFFu, v, o);
    return v;
}
__device__ __forceinline__ float wmax32(float v) {
#pragma unroll
    for (int o = 16; o; o >>= 1) v = fmaxf(v, __shfl_xor_sync(0xFFFFFFFFu, v, o));
    return v;
}

// =====================================================================
// Pass 1: s0 = (1/32)*sum_i u ; v0 = squash(s0 + bias)
// =====================================================================
__global__ void __launch_bounds__(256) pass1_kernel(const float* __restrict__ u,
                                                    const float* __restrict__ bias) {
    __shared__ float sred[64 * 17];
    int j = blockIdx.x, b = blockIdx.y;
    int t = threadIdx.x;
    int q = t & 3, ir = t >> 2;
    const float* base = u + (size_t)(b * NJ + j) * (NI * NN);
    float4 acc = make_float4(0.f, 0.f, 0.f, 0.f);
#pragma unroll
    for (int k = 0; k < 18; ++k) {
        int i = ir + k * 64;
        float4 v = *reinterpret_cast<const float4*>(base + (size_t)i * NN + q * 4);
        acc.x += v.x; acc.y += v.y; acc.z += v.z; acc.w += v.w;
    }
    float* sp = sred + ir * 17 + q * 4;
    sp[0] = acc.x; sp[1] = acc.y; sp[2] = acc.z; sp[3] = acc.w;
    __syncthreads();
    if (t < 16) {
        int n = t;
        float s = 0.f;
        for (int r = 0; r < 64; ++r) s += sred[r * 17 + n];
        s *= (1.f / 32.f);
        float ss = s;
#pragma unroll
        for (int o = 8; o; o >>= 1) ss += __shfl_xor_sync(0xFFFFu, ss, o);
        float tb = (ss == 0.f) ? 0.f : (s + bias[j * NN + n]);
        float sq = tb * tb;
#pragma unroll
        for (int o = 8; o; o >>= 1) sq += __shfl_xor_sync(0xFFFFu, sq, o);
        float v = (sq / (1.f + sq)) * tb / sqrtf(sq + 1e-8f);
        g_V0[(b * NJ + j) * NN + n] = v;
    }
}

// =====================================================================
// Unified streaming sweep over selected j only (compacted list).
//  SCORE (!IS_SUM): register dots -> masked softmax -> node-score partials
//  SUM   ( IS_SUM): pipelined per-8-row groups: dots -> softmax(+entropy)
//                   -> s-accum from register-held u; s partials out.
// KSEL = exact number of selected capsules (32 / 20 / 12).
// =====================================================================
template <int KSEL, bool IS_SUM>
__global__ void __launch_bounds__(256) stream_kernel(const float* __restrict__ u,
                                                     const float* __restrict__ vglob,
                                                     const unsigned* __restrict__ maskp,
                                                     int ent_slot) {
    constexpr int SLOTS = (KSEL + 7) / 8;
    __shared__ float sd[32 * DSTR];
    __shared__ int   sj[32];
    __shared__ float red[8];
    int t = threadIdx.x, lane = t & 31, w = t >> 5;
    int tb = blockIdx.x, b = blockIdx.y, i0 = tb * TI;
    int q = lane & 3, ig = lane >> 2;
    unsigned msk = maskp ? maskp[b] : 0xFFFFFFFFu;
    if (t < 32 && ((msk >> t) & 1u))
        sj[__popc(msk & ((1u << t) - 1u))] = t;
    __syncthreads();

    const float* ub = u + (size_t)b * (NJ * NI * NN);

    int   jl[SLOTS];
    bool  act[SLOTS];
    float4 vj[SLOTS];
#pragma unroll
    for (int sl = 0; sl < SLOTS; ++sl) {
        act[sl] = (sl * 8 + w) < KSEL;
        jl[sl]  = act[sl] ? sj[sl * 8 + w] : 0;
        vj[sl]  = act[sl] ? *reinterpret_cast<const float4*>(vglob + (b * NJ + jl[sl]) * NN + q * 4)
                          : make_float4(0.f, 0.f, 0.f, 0.f);
    }

    if (!IS_SUM) {
        // ---- SCORE path ----
#pragma unroll
        for (int sl = 0; sl < SLOTS; ++sl) if (act[sl]) {
            const float* base = ub + (size_t)jl[sl] * (NI * NN) + (size_t)i0 * NN + q * 4;
#pragma unroll
            for (int m = 0; m < 4; ++m) {
                int il = m * 8 + ig;
                float4 r = *reinterpret_cast<const float4*>(base + (size_t)il * NN);
                float d = r.x * vj[sl].x + r.y * vj[sl].y + r.z * vj[sl].z + r.w * vj[sl].w;
                d += __shfl_xor_sync(0xFFFFFFFFu, d, 1);
                d += __shfl_xor_sync(0xFFFFFFFFu, d, 2);
                if (q == 0) sd[il * DSTR + jl[sl]] = d;
            }
        }
        __syncthreads();
#pragma unroll
        for (int s = 0; s < 4; ++s) {
            int il = w * 4 + s;
            float d = sd[il * DSTR + lane];
            bool sel = (msk >> lane) & 1u;
            float mx = wmax32(sel ? d : -INFINITY);
            float e = sel ? expf(d - mx) : 0.f;
            float S = wsum32(e);
            sd[il * DSTR + lane] = e / S;
        }
        __syncthreads();
#pragma unroll
        for (int p = 0; p < 4; ++p) {
            int j = w * 4 + p;
            bool selj = (msk >> j) & 1u;
            float c = wsum32(selj ? sd[lane * DSTR + j] : 0.f);
            if (lane == 0) g_sc_part[tb * (NB * NJ) + b * NJ + j] = c;
        }
    } else {
        // ---- SUM path (register-pipelined) ----
        float4 rcur[SLOTS], rnxt[SLOTS], acc[SLOTS];
#pragma unroll
        for (int sl = 0; sl < SLOTS; ++sl) {
            acc[sl] = make_float4(0.f, 0.f, 0.f, 0.f);
            rcur[sl] = act[sl] ? *reinterpret_cast<const float4*>(
                           ub + (size_t)jl[sl] * (NI * NN) + (size_t)(i0 + ig) * NN + q * 4)
                               : make_float4(0.f, 0.f, 0.f, 0.f);
        }
        float ent_acc = 0.f;
#pragma unroll
        for (int m = 0; m < 4; ++m) {
            int il = m * 8 + ig;
#pragma unroll
            for (int sl = 0; sl < SLOTS; ++sl) if (act[sl]) {
                float4 r = rcur[sl];
                float d = r.x * vj[sl].x + r.y * vj[sl].y + r.z * vj[sl].z + r.w * vj[sl].w;
                d += __shfl_xor_sync(0xFFFFFFFFu, d, 1);
                d += __shfl_xor_sync(0xFFFFFFFFu, d, 2);
                if (q == 0) sd[il * DSTR + jl[sl]] = d;
            }
            if (m < 3) {
                int iln = (m + 1) * 8 + ig;
#pragma unroll
                for (int sl = 0; sl < SLOTS; ++sl)
                    rnxt[sl] = act[sl] ? *reinterpret_cast<const float4*>(
                                   ub + (size_t)jl[sl] * (NI * NN) + (size_t)(i0 + iln) * NN + q * 4)
                                       : make_float4(0.f, 0.f, 0.f, 0.f);
            }
            __syncthreads();
            {
                int il2 = m * 8 + w;
                float d = sd[il2 * DSTR + lane];
                bool sel = (msk >> lane) & 1u;
                float mx = wmax32(sel ? d : -INFINITY);
                float e = sel ? expf(d - mx) : 0.f;
                float S = wsum32(e);
                float c = e / S;
                sd[il2 * DSTR + lane] = c;
                float cds = wsum32(sel ? c * d : 0.f);
                ent_acc += (mx + logf(S) - cds);
            }
            __syncthreads();
#pragma unroll
            for (int sl = 0; sl < SLOTS; ++sl) if (act[sl]) {
                float c = sd[il * DSTR + jl[sl]];
                acc[sl].x += c * rcur[sl].x;
                acc[sl].y += c * rcur[sl].y;
                acc[sl].z += c * rcur[sl].z;
                acc[sl].w += c * rcur[sl].w;
            }
#pragma unroll
            for (int sl = 0; sl < SLOTS; ++sl) rcur[sl] = rnxt[sl];
        }
#pragma unroll
        for (int sl = 0; sl < SLOTS; ++sl) {
#pragma unroll
            for (int o = 4; o < 32; o <<= 1) {
                acc[sl].x += __shfl_xor_sync(0xFFFFFFFFu, acc[sl].x, o);
                acc[sl].y += __shfl_xor_sync(0xFFFFFFFFu, acc[sl].y, o);
                acc[sl].z += __shfl_xor_sync(0xFFFFFFFFu, acc[sl].z, o);
                acc[sl].w += __shfl_xor_sync(0xFFFFFFFFu, acc[sl].w, o);
            }
            if (ig == 0 && act[sl]) {
                size_t so = (size_t)tb * (NB * NJ * NN) + (size_t)(b * NJ + jl[sl]) * NN + q * 4;
                *reinterpret_cast<float4*>(g_S_part + so) = acc[sl];
            }
        }
        if (lane == 0) red[w] = ent_acc;
        __syncthreads();
        if (t == 0) {
            float e = 0.f;
#pragma unroll
            for (int x = 0; x < 8; ++x) e += red[x];
            g_ent_part[ent_slot * (NTILES * NB) + tb * NB + b] = e;
        }
    }
}

// =====================================================================
// top-k per example (tie-break: lower index wins)
// =====================================================================
__global__ void topk_kernel(int K, int which) {
    int b = blockIdx.x, j = threadIdx.x;
    float sc = 0.f;
#pragma unroll 6
    for (int tt = 0; tt < NTILES; ++tt) sc += g_sc_part[tt * (NB * NJ) + b * NJ + j];
    int rank = 0;
#pragma unroll
    for (int k = 0; k < 32; ++k) {
        float o = __shfl_sync(0xFFFFFFFFu, sc, k);
        rank += (o > sc) || (o == sc && k < j);
    }
    unsigned m = __ballot_sync(0xFFFFFFFFu, rank < K);
    if (j == 0) {
        if (which == 1) g_mask1[b] = m; else g_mask2[b] = m;
    }
}

// =====================================================================
// squash from s partials (mask-aware; unselected capsules -> v = 0)
// =====================================================================
__device__ __forceinline__ float squash_elem(int gid, bool sel, const float* __restrict__ bias) {
    float s = 0.f;
    if (sel) {
#pragma unroll 6
        for (int tt = 0; tt < NTILES; ++tt) s += g_S_part[(size_t)tt * (NB * NJ * NN) + gid];
    }
    float ss = s;
#pragma unroll
    for (int o = 8; o; o >>= 1) ss += __shfl_xor_sync(0xFFFFFFFFu, ss, o);
    int n = gid & 15, j = (gid >> 4) & 31;
    float tb = (ss == 0.f) ? 0.f : (s + bias[j * NN + n]);
    float sq = tb * tb;
#pragma unroll
    for (int o = 8; o; o >>= 1) sq += __shfl_xor_sync(0xFFFFFFFFu, sq, o);
    return (sq == 0.f) ? 0.f : (sq / (1.f + sq)) * tb / sqrtf(sq + 1e-8f);
}

__global__ void __launch_bounds__(256) squash_mid_kernel(const float* __restrict__ bias) {
    int gid = blockIdx.x * 256 + threadIdx.x;
    int j = (gid >> 4) & 31, b = gid >> 9;
    bool sel = (g_mask1[b] >> j) & 1u;
    float v = squash_elem(gid, sel, bias);
    g_V1[gid] = v;
    g_VW[gid] = g_V0[gid] + v;
}

__global__ void __launch_bounds__(256) final_kernel(const float* __restrict__ bias,
                                                    float* __restrict__ out, int out_size) {
    int gid = blockIdx.x * 256 + threadIdx.x;
    int j = (gid >> 4) & 31, b = gid >> 9;
    bool sel = (g_mask2[b] >> j) & 1u;
    out[gid] = squash_elem(gid, sel, bias);
    if (blockIdx.x == 0 && threadIdx.x < NB && out_size >= NB * NJ * NN + NB * 3) {
        int bb = threadIdx.x;
        float e1 = 0.f, e2 = 0.f;
        for (int tt = 0; tt < NTILES; ++tt) {
            e1 += g_ent_part[0 * (NTILES * NB) + tt * NB + bb];
            e2 += g_ent_part[1 * (NTILES * NB) + tt * NB + bb];
        }
        float* eo = out + NB * NJ * NN;
        eo[bb * 3 + 0] = logf(32.0f);
        eo[bb * 3 + 1] = e1 * (1.f / (float)NI);
        eo[bb * 3 + 2] = e2 * (1.f / (float)NI);
    }
}

// =====================================================================
extern "C" void kernel_launch(void* const* d_in, const int* in_sizes, int n_in,
                              void* d_out, int out_size) {
    const float* u    = (const float*)d_in[0];
    const float* bias = (const float*)d_in[1];
    float* out        = (float*)d_out;

    float *v0p, *vwp;
    unsigned *m1p, *m2p;
    cudaGetSymbolAddress((void**)&v0p, g_V0);
    cudaGetSymbolAddress((void**)&vwp, g_VW);
    cudaGetSymbolAddress((void**)&m1p, g_mask1);
    cudaGetSymbolAddress((void**)&m2p, g_mask2);

    dim3 sgrid(NTILES, NB);

    // sweep 1 (302 MB): s0 -> v0
    pass1_kernel<<<dim3(NJ, NB), 256>>>(u, bias);
    // sweep 2 (302 MB): scores of softmax(u·v0) -> top-20 -> mask1
    stream_kernel<32, false><<<sgrid, 256>>>(u, v0p, nullptr, 0);
    topk_kernel<<<NB, 32>>>(20, 1);
    // sweep 3 (189 MB, 20 j only): c1, entropy1, s1 -> v1, w = v0 + v1
    stream_kernel<20, true><<<sgrid, 256>>>(u, v0p, m1p, 0);
    squash_mid_kernel<<<256, 256>>>(bias);
    // sweep 4 (189 MB, 20 j only): scores of softmax(u·w, mask1) -> top-12 -> mask2
    stream_kernel<20, false><<<sgrid, 256>>>(u, vwp, m1p, 0);
    topk_kernel<<<NB, 32>>>(12, 2);
    // sweep 5 (113 MB, 12 j only): c2, entropy2, s2 -> v2 (out)
    stream_kernel<12, true><<<sgrid, 256>>>(u, vwp, m2p, 1);
    final_kernel<<<256, 256>>>(bias, out, out_size);
}